// round 1
// baseline (speedup 1.0000x reference)
#include <cuda_runtime.h>
#include <math.h>

#define NMAX 100000
#define EMAX 3200000
#define H 32
#define GMAX 128
#define SCAN_BLK 1024

// ---------------- static scratch (no allocation allowed) ----------------
__device__ int   g_count[NMAX];      // per-node in-degree (excl self loop)
__device__ int   g_off[NMAX];        // CSR offsets (exclusive)
__device__ int   g_cursor[NMAX];     // scatter cursors
__device__ int   g_csr[EMAX];        // CSR source indices
__device__ int   g_bsum[256];        // scan block sums
__device__ float g_dinv[NMAX];       // rsqrt(deg)
__device__ float g_bufA[NMAX * H];
__device__ float g_bufB[NMAX * H];
__device__ float g_gsum[GMAX * H];
__device__ float g_gcnt[GMAX];

// ---------------- setup kernels ----------------
__global__ void k_zero(int n, int g) {
    int t = blockIdx.x * blockDim.x + threadIdx.x;
    if (t < n) g_count[t] = 0;
    if (t < g * H) g_gsum[t] = 0.f;
    if (t < g) g_gcnt[t] = 0.f;
}

__global__ void k_hist(const int* __restrict__ edge, int E) {
    int e = blockIdx.x * blockDim.x + threadIdx.x;
    if (e >= E) return;
    atomicAdd(&g_count[edge[E + e]], 1);   // dst row
}

__global__ void k_scan1(int n) {
    __shared__ int s[SCAN_BLK];
    int tid = threadIdx.x;
    int i = blockIdx.x * SCAN_BLK + tid;
    int v = (i < n) ? g_count[i] : 0;
    s[tid] = v;
    __syncthreads();
    for (int d = 1; d < SCAN_BLK; d <<= 1) {
        int t = (tid >= d) ? s[tid - d] : 0;
        __syncthreads();
        s[tid] += t;
        __syncthreads();
    }
    if (i < n) g_off[i] = s[tid] - v;          // exclusive within block
    if (tid == SCAN_BLK - 1) g_bsum[blockIdx.x] = s[tid];
}

__global__ void k_scan2(int nblk) {
    if (threadIdx.x == 0 && blockIdx.x == 0) {
        int acc = 0;
        for (int b = 0; b < nblk; b++) { int v = g_bsum[b]; g_bsum[b] = acc; acc += v; }
    }
}

__global__ void k_scan3(int n) {
    int i = blockIdx.x * blockDim.x + threadIdx.x;
    if (i >= n) return;
    int o = g_off[i] + g_bsum[i / SCAN_BLK];
    g_off[i] = o;
    g_cursor[i] = o;
    g_dinv[i] = rsqrtf((float)(g_count[i] + 1));   // +1 for self loop
}

__global__ void k_scatter(const int* __restrict__ edge, int E) {
    int e = blockIdx.x * blockDim.x + threadIdx.x;
    if (e >= E) return;
    int s = edge[e];
    int d = edge[E + e];
    int pos = atomicAdd(&g_cursor[d], 1);
    g_csr[pos] = s;
}

// y1[i][k] = x[i] * W1[k] * dinv[i]
__global__ void k_prep1(const float* __restrict__ x, const float* __restrict__ W1,
                        float* __restrict__ yout, int n) {
    int t = blockIdx.x * blockDim.x + threadIdx.x;
    if (t >= n * H) return;
    int i = t >> 5, k = t & 31;
    yout[t] = x[i] * W1[k] * g_dinv[i];
}

// ---------------- aggregation core (one warp = one node, lane = column) ----
__device__ __forceinline__ float agg_node(const float* __restrict__ yin,
                                          int i, int lane) {
    int beg = g_off[i];
    int cnt = g_count[i];
    float acc = yin[i * H + lane];   // self loop (norm dinv^2 applied outside)
    int c = 0;
    while (c < cnt) {
        int m = cnt - c; if (m > 32) m = 32;
        int idx = 0;
        if (lane < m) idx = g_csr[beg + c + lane];
        if (m == 32) {
            #pragma unroll
            for (int j = 0; j < 32; j++) {
                int s = __shfl_sync(0xffffffffu, idx, j);
                acc += yin[s * H + lane];
            }
        } else {
            for (int j = 0; j < m; j++) {
                int s = __shfl_sync(0xffffffffu, idx, j);
                acc += yin[s * H + lane];
            }
        }
        c += 32;
    }
    return acc;
}

// Layers 1 & 2: h = relu(dinv*agg + b); y_out = (h @ Wnext) * dinv
__global__ void k_layer_mid(const float* __restrict__ yin, float* __restrict__ yout,
                            const float* __restrict__ b, const float* __restrict__ Wn,
                            int n) {
    __shared__ float sW[H * H];
    __shared__ float sb[H];
    int tid = threadIdx.x;
    for (int t = tid; t < H * H; t += blockDim.x) sW[t] = Wn[t];
    if (tid < H) sb[tid] = b[tid];
    __syncthreads();
    int warp = (blockIdx.x * blockDim.x + tid) >> 5;
    int lane = tid & 31;
    if (warp >= n) return;
    float dv = g_dinv[warp];
    float acc = agg_node(yin, warp, lane);
    float h = fmaxf(dv * acc + sb[lane], 0.f);
    float o = 0.f;
    #pragma unroll
    for (int j = 0; j < H; j++)
        o += __shfl_sync(0xffffffffu, h, j) * sW[j * H + lane];
    yout[warp * H + lane] = o * dv;
}

// Layer 3 + theta head fused
__global__ void k_layer3(const float* __restrict__ yin, float* __restrict__ hout,
                         float* __restrict__ theta_out,
                         const float* __restrict__ b3,
                         const float* __restrict__ Wt1, const float* __restrict__ bt1,
                         const float* __restrict__ Wt2, const float* __restrict__ bt2,
                         int n) {
    __shared__ float sW[H * H];
    __shared__ float sb[H], sbt1[H], swt2[H];
    __shared__ float sbt2;
    int tid = threadIdx.x;
    for (int t = tid; t < H * H; t += blockDim.x) sW[t] = Wt1[t];
    if (tid < H) { sb[tid] = b3[tid]; sbt1[tid] = bt1[tid]; swt2[tid] = Wt2[tid]; }
    if (tid == 0) sbt2 = bt2[0];
    __syncthreads();
    int warp = (blockIdx.x * blockDim.x + tid) >> 5;
    int lane = tid & 31;
    if (warp >= n) return;
    float dv = g_dinv[warp];
    float acc = agg_node(yin, warp, lane);
    float h = fmaxf(dv * acc + sb[lane], 0.f);
    hout[warp * H + lane] = h;
    // theta head: t1 = relu(h @ Wt1 + bt1); p = t1 @ Wt2 + bt2; theta = PI*sigmoid(p)
    float t1 = sbt1[lane];
    #pragma unroll
    for (int j = 0; j < H; j++)
        t1 += __shfl_sync(0xffffffffu, h, j) * sW[j * H + lane];
    t1 = fmaxf(t1, 0.f);
    float p = t1 * swt2[lane];
    #pragma unroll
    for (int d = 16; d > 0; d >>= 1) p += __shfl_xor_sync(0xffffffffu, p, d);
    if (lane == 0) {
        float v = p + sbt2;
        theta_out[warp] = 3.14159265358979323846f / (1.f + expf(-v));
    }
}

// Pooling: batch is sorted -> each warp owns a contiguous node range, flush on change
__global__ void k_pool(const float* __restrict__ h, const int* __restrict__ batch, int n) {
    int gw = (blockIdx.x * blockDim.x + threadIdx.x) >> 5;
    int lane = threadIdx.x & 31;
    int nwarps = (gridDim.x * blockDim.x) >> 5;
    int chunk = (n + nwarps - 1) / nwarps;
    int start = gw * chunk;
    int end = start + chunk; if (end > n) end = n;
    if (start >= end) return;
    int cur = batch[start];
    float acc = 0.f, cnt = 0.f;
    for (int i = start; i < end; i++) {
        int bg = batch[i];
        if (bg != cur) {
            atomicAdd(&g_gsum[cur * H + lane], acc);
            if (lane == 0) atomicAdd(&g_gcnt[cur], cnt);
            acc = 0.f; cnt = 0.f; cur = bg;
        }
        acc += h[i * H + lane];
        cnt += 1.f;
    }
    atomicAdd(&g_gsum[cur * H + lane], acc);
    if (lane == 0) atomicAdd(&g_gcnt[cur], cnt);
}

// Graph head: one thread per graph
__global__ void k_ghead(float* __restrict__ out_bg,
                        const float* __restrict__ Wg1, const float* __restrict__ bg1,
                        const float* __restrict__ Wg2, const float* __restrict__ bg2,
                        int G) {
    __shared__ float sW1[H * H], sb1[H], sW2[H * 2], sb2[2];
    int tid = threadIdx.x;
    for (int t = tid; t < H * H; t += blockDim.x) sW1[t] = Wg1[t];
    if (tid < H) { sb1[tid] = bg1[tid]; sW2[tid * 2] = Wg2[tid * 2]; sW2[tid * 2 + 1] = Wg2[tid * 2 + 1]; }
    if (tid < 2) sb2[tid] = bg2[tid];
    __syncthreads();
    int g = tid;
    if (g >= G) return;
    float cg = g_gcnt[g]; if (cg < 1.f) cg = 1.f;
    float e[H];
    #pragma unroll
    for (int k = 0; k < H; k++) e[k] = g_gsum[g * H + k] / cg;
    float z[H];
    #pragma unroll
    for (int k = 0; k < H; k++) {
        float s = sb1[k];
        #pragma unroll
        for (int j = 0; j < H; j++) s += e[j] * sW1[j * H + k];
        z[k] = fmaxf(s, 0.f);
    }
    #pragma unroll
    for (int j2 = 0; j2 < 2; j2++) {
        float s = sb2[j2];
        #pragma unroll
        for (int k = 0; k < H; k++) s += z[k] * sW2[k * 2 + j2];
        out_bg[g * 2 + j2] = 2.f * 3.14159265358979323846f / (1.f + expf(-s));
    }
}

// ---------------- launch ----------------
extern "C" void kernel_launch(void* const* d_in, const int* in_sizes, int n_in,
                              void* d_out, int out_size) {
    const float* x    = (const float*)d_in[0];
    const int*   edge = (const int*)d_in[1];
    const int*   batch= (const int*)d_in[2];
    const float* W1   = (const float*)d_in[3];
    const float* b1   = (const float*)d_in[4];
    const float* W2   = (const float*)d_in[5];
    const float* b2   = (const float*)d_in[6];
    const float* W3   = (const float*)d_in[7];
    const float* b3   = (const float*)d_in[8];
    const float* Wt1  = (const float*)d_in[9];
    const float* bt1  = (const float*)d_in[10];
    const float* Wt2  = (const float*)d_in[11];
    const float* bt2  = (const float*)d_in[12];
    const float* Wg1  = (const float*)d_in[13];
    const float* bg1  = (const float*)d_in[14];
    const float* Wg2  = (const float*)d_in[15];
    const float* bg2  = (const float*)d_in[16];

    int N = in_sizes[0];
    int E = in_sizes[1] / 2;
    int G = (out_size - N) / 2;
    float* out = (float*)d_out;

    float *bufA, *bufB;
    cudaGetSymbolAddress((void**)&bufA, g_bufA);
    cudaGetSymbolAddress((void**)&bufB, g_bufB);

    int nblk_scan = (N + SCAN_BLK - 1) / SCAN_BLK;

    k_zero<<<(N + 255) / 256, 256>>>(N, G);
    k_hist<<<(E + 255) / 256, 256>>>(edge, E);
    k_scan1<<<nblk_scan, SCAN_BLK>>>(N);
    k_scan2<<<1, 32>>>(nblk_scan);
    k_scan3<<<(N + 255) / 256, 256>>>(N);
    k_scatter<<<(E + 255) / 256, 256>>>(edge, E);
    k_prep1<<<(N * H + 255) / 256, 256>>>(x, W1, bufA, N);

    int layer_blocks = (N * 32 + 255) / 256;
    k_layer_mid<<<layer_blocks, 256>>>(bufA, bufB, b1, W2, N);
    k_layer_mid<<<layer_blocks, 256>>>(bufB, bufA, b2, W3, N);
    k_layer3<<<layer_blocks, 256>>>(bufA, bufB, out, b3, Wt1, bt1, Wt2, bt2, N);

    k_pool<<<256, 256>>>(bufB, batch, N);
    k_ghead<<<1, 128>>>(out + N, Wg1, bg1, Wg2, bg2, G);
}